// round 6
// baseline (speedup 1.0000x reference)
#include <cuda_runtime.h>

#define NPTS     200000
#define NREL     128
#define SCT_PTS  1024
#define NBLK     ((NPTS + SCT_PTS - 1) / SCT_PTS)   // 196
#define CELLCAP  32        // per-(relation, window) capacity; mean 8, sd 2.8
#define GRID_MAIN (152 * 8)  // one full wave at 8 CTAs/SM
#define WPC      4

// ---- device scratch (no allocations). Everything below is rewritten by
//      k_scatter each launch (or never consumed past the written count),
//      so no reset kernel is needed. ----
__device__ int g_cellcnt[NREL * NBLK];
__device__ int g_cursor[NREL];
__device__ int g_pids[NREL * NBLK * CELLCAP];

// Scatter: window blk bins its 1024 points into its OWN fixed cell per
// relation (plain stores, no global atomics). Block 0 rezeroes the
// work-stealing cursors. Overflow beyond CELLCAP (>8 sigma) computed inline.
__global__ void __launch_bounds__(256)
k_scatter(const int* __restrict__ rel, int n,
          const float* __restrict__ x,
          const float* __restrict__ w,
          float* __restrict__ out) {
    __shared__ int s_rel[SCT_PTS];
    __shared__ int s_hist[NREL];
    __shared__ int s_cur[NREL];

    int blk = blockIdx.x;
    if (blk == 0) {
        for (int i = threadIdx.x; i < NREL; i += blockDim.x) g_cursor[i] = 0;
    }

    int start = blk * SCT_PTS;
    int cnt = n - start;
    if (cnt > SCT_PTS) cnt = SCT_PTS;

    for (int i = threadIdx.x; i < NREL; i += blockDim.x) {
        s_hist[i] = 0;
        s_cur[i]  = 0;
    }
    __syncthreads();

    for (int i = threadIdx.x; i < cnt; i += blockDim.x) {
        int r = __ldg(rel + start + i);
        s_rel[i] = r;
        atomicAdd(&s_hist[r], 1);
    }
    __syncthreads();

    for (int i = threadIdx.x; i < NREL; i += blockDim.x) {
        int c = s_hist[i];
        g_cellcnt[i * NBLK + blk] = (c > CELLCAP) ? CELLCAP : c;
    }
    __syncthreads();

    for (int i = threadIdx.x; i < cnt; i += blockDim.x) {
        int r = s_rel[i];
        int pos = atomicAdd(&s_cur[r], 1);
        int p = start + i;
        if (pos < CELLCAP) {
            g_pids[(r * NBLK + blk) * CELLCAP + pos] = p;
        } else {
            // Dead-in-practice overflow: compute this point directly.
            const float* xr = x + (size_t)p * 128;
            float* orow = out + (size_t)p * 128;
            for (int bb = 0; bb < 16; bb++) {
                const float* wb = w + (size_t)((r * 16 + bb) * 8) * 8;
                for (int o = 0; o < 8; o++) {
                    float acc = 0.f;
                    for (int ii = 0; ii < 8; ii++)
                        acc = fmaf(xr[bb * 8 + ii], wb[ii * 8 + o], acc);
                    orow[bb * 8 + o] = acc;
                }
            }
        }
    }
}

// Main: one wave (1216 CTAs x 4 warps = 38 warps per relation). Lane
// (2b+h) owns block b, output-half h. Per point: ONE contiguous 512B row
// LDG (lane reads row float4[lane] = its own-half inputs), a 4-float
// shfl_xor(1) exchange supplies the partner-half inputs, weights are
// pre-grouped per lane as own-half (wtO) / partner-half (wtP) so the
// exchange costs no extra ALU. Cells are work-stolen with DEPTH-2
// prefetch: steal atomic + cnt/pid loads for cell C issue while cell A is
// processed, fully covering the ~1000-cycle dependency chain.
__global__ void __launch_bounds__(32 * WPC, 8)
k_main(const float4* __restrict__ x4,
       const float4* __restrict__ w4,
       float4* __restrict__ out4,
       int ncell) {
    int gw   = blockIdx.x * WPC + (threadIdx.x >> 5);
    int r    = gw & (NREL - 1);
    int lane = threadIdx.x & 31;
    int b    = lane >> 1;
    int h    = lane & 1;

    // wtO[i][j] = W[r][b][4h+i][4h+j]   (own-half inputs)
    // wtP[i][j] = W[r][b][4(1-h)+i][4h+j] (partner-half inputs)
    int wbase = (r * 16 + b) * 8;
    float4 wtO[4], wtP[4];
#pragma unroll
    for (int i = 0; i < 4; i++) {
        wtO[i] = __ldg(w4 + (size_t)(wbase + 4 * h + i) * 2 + h);
        wtP[i] = __ldg(w4 + (size_t)(wbase + 4 - 4 * h + i) * 2 + h);
    }

#define STEAL(C)                                                     \
    {                                                                \
        int t = 0;                                                   \
        if (lane == 0) t = atomicAdd(&g_cursor[r], 1);               \
        (C) = __shfl_sync(0xffffffffu, t, 0);                        \
    }

    int cA, cB, cC;
    int cntA = 0, cntB = 0, cntC;
    int pidA = 0, pidB = 0, pidC;

    STEAL(cA)
    if (cA < ncell) {
        int ci = r * NBLK + cA;
        cntA = __ldg(&g_cellcnt[ci]);
        pidA = __ldg(g_pids + (size_t)ci * CELLCAP + lane);
    }
    STEAL(cB)
    if (cB < ncell) {
        int ci = r * NBLK + cB;
        cntB = __ldg(&g_cellcnt[ci]);
        pidB = __ldg(g_pids + (size_t)ci * CELLCAP + lane);
    }

    while (cA < ncell) {
        // prefetch cell C (depth-2: consumed two iterations from now)
        STEAL(cC)
        cntC = 0; pidC = 0;
        if (cC < ncell) {
            int ci = r * NBLK + cC;
            cntC = __ldg(&g_cellcnt[ci]);
            pidC = __ldg(g_pids + (size_t)ci * CELLCAP + lane);
        }

#define DO_POINT(P, V)                                                       \
        {                                                                    \
            float q0 = __shfl_xor_sync(0xffffffffu, (V).x, 1);               \
            float q1 = __shfl_xor_sync(0xffffffffu, (V).y, 1);               \
            float q2 = __shfl_xor_sync(0xffffffffu, (V).z, 1);               \
            float q3 = __shfl_xor_sync(0xffffffffu, (V).w, 1);               \
            float vs[4] = {(V).x, (V).y, (V).z, (V).w};                      \
            float qs[4] = {q0, q1, q2, q3};                                  \
            float a0 = 0.f, a1 = 0.f, a2 = 0.f, a3 = 0.f;                    \
            _Pragma("unroll")                                                \
            for (int i = 0; i < 4; i++) {                                    \
                a0 = fmaf(vs[i], wtO[i].x, a0);                              \
                a1 = fmaf(vs[i], wtO[i].y, a1);                              \
                a2 = fmaf(vs[i], wtO[i].z, a2);                              \
                a3 = fmaf(vs[i], wtO[i].w, a3);                              \
            }                                                                \
            _Pragma("unroll")                                                \
            for (int i = 0; i < 4; i++) {                                    \
                a0 = fmaf(qs[i], wtP[i].x, a0);                              \
                a1 = fmaf(qs[i], wtP[i].y, a1);                              \
                a2 = fmaf(qs[i], wtP[i].z, a2);                              \
                a3 = fmaf(qs[i], wtP[i].w, a3);                              \
            }                                                                \
            out4[(size_t)(P) * 32 + lane] = make_float4(a0, a1, a2, a3);     \
        }

        // process cell A (unroll-4: 4 independent 512B row loads in flight)
        int k = 0;
        for (; k + 4 <= cntA; k += 4) {
            int p0 = __shfl_sync(0xffffffffu, pidA, k);
            int p1 = __shfl_sync(0xffffffffu, pidA, k + 1);
            int p2 = __shfl_sync(0xffffffffu, pidA, k + 2);
            int p3 = __shfl_sync(0xffffffffu, pidA, k + 3);
            float4 v0 = __ldg(x4 + (size_t)p0 * 32 + lane);
            float4 v1 = __ldg(x4 + (size_t)p1 * 32 + lane);
            float4 v2 = __ldg(x4 + (size_t)p2 * 32 + lane);
            float4 v3 = __ldg(x4 + (size_t)p3 * 32 + lane);
            DO_POINT(p0, v0)
            DO_POINT(p1, v1)
            DO_POINT(p2, v2)
            DO_POINT(p3, v3)
        }
        for (; k < cntA; k++) {
            int p = __shfl_sync(0xffffffffu, pidA, k);
            float4 v = __ldg(x4 + (size_t)p * 32 + lane);
            DO_POINT(p, v)
        }
#undef DO_POINT

        cA = cB; cntA = cntB; pidA = pidB;
        cB = cC; cntB = cntC; pidB = pidC;
    }
#undef STEAL
}

extern "C" void kernel_launch(void* const* d_in, const int* in_sizes, int n_in,
                              void* d_out, int out_size) {
    const float* x      = (const float*)d_in[0];   // [NPTS, 128] f32
    const float* blocks = (const float*)d_in[1];   // [128,16,8,8] f32
    const int*   rel    = (const int*)d_in[2];     // [NPTS] i32
    int n = in_sizes[2];
    if (n > NPTS) n = NPTS;  // scratch bound

    int nblk = (n + SCT_PTS - 1) / SCT_PTS;        // 196
    k_scatter<<<NBLK, 256>>>(rel, n, x, blocks, (float*)d_out);
    k_main<<<GRID_MAIN, 32 * WPC>>>(
        (const float4*)x, (const float4*)blocks, (float4*)d_out, nblk);
}

// round 7
// speedup vs baseline: 1.2513x; 1.2513x over previous
#include <cuda_runtime.h>

#define NPTS     200000
#define NREL     128
#define SCT_PTS  1024
#define NBLK     ((NPTS + SCT_PTS - 1) / SCT_PTS)   // 196
#define CELLCAP  32          // per-(relation, window) capacity; mean 8, sd 2.8
#define CTAS_PER_REL 6
#define GRID_MAIN (NREL * CTAS_PER_REL)   // 768 CTAs, single wave
#define THREADS  256
#define WSTRIDE  36          // words per lane in smem weight tile (bank swizzle)

// ---- device scratch (no allocations). Everything below is rewritten by
//      k_scatter each launch (or never consumed past the written count). ----
__device__ int g_cellcnt[NREL * NBLK];
__device__ int g_cursor[NREL];
__device__ int g_pids[NREL * NBLK * CELLCAP];

// Scatter: window blk bins its 1024 points into its OWN fixed cell per
// relation (plain stores, no global atomics). Block 0 rezeroes the
// work-stealing cursors. Overflow beyond CELLCAP (>8 sigma) computed inline.
__global__ void __launch_bounds__(256)
k_scatter(const int* __restrict__ rel, int n,
          const float* __restrict__ x,
          const float* __restrict__ w,
          float* __restrict__ out) {
    __shared__ int s_rel[SCT_PTS];
    __shared__ int s_hist[NREL];
    __shared__ int s_cur[NREL];

    int blk = blockIdx.x;
    if (blk == 0) {
        for (int i = threadIdx.x; i < NREL; i += blockDim.x) g_cursor[i] = 0;
    }

    int start = blk * SCT_PTS;
    int cnt = n - start;
    if (cnt > SCT_PTS) cnt = SCT_PTS;

    for (int i = threadIdx.x; i < NREL; i += blockDim.x) {
        s_hist[i] = 0;
        s_cur[i]  = 0;
    }
    __syncthreads();

    for (int i = threadIdx.x; i < cnt; i += blockDim.x) {
        int r = __ldg(rel + start + i);
        s_rel[i] = r;
        atomicAdd(&s_hist[r], 1);
    }
    __syncthreads();

    for (int i = threadIdx.x; i < NREL; i += blockDim.x) {
        int c = s_hist[i];
        g_cellcnt[i * NBLK + blk] = (c > CELLCAP) ? CELLCAP : c;
    }
    __syncthreads();

    for (int i = threadIdx.x; i < cnt; i += blockDim.x) {
        int r = s_rel[i];
        int pos = atomicAdd(&s_cur[r], 1);
        int p = start + i;
        if (pos < CELLCAP) {
            g_pids[(r * NBLK + blk) * CELLCAP + pos] = p;
        } else {
            // Dead-in-practice overflow: compute this point directly.
            const float* xr = x + (size_t)p * 128;
            float* orow = out + (size_t)p * 128;
            for (int bb = 0; bb < 16; bb++) {
                const float* wb = w + (size_t)((r * 16 + bb) * 8) * 8;
                for (int o = 0; o < 8; o++) {
                    float acc = 0.f;
                    for (int ii = 0; ii < 8; ii++)
                        acc = fmaf(xr[bb * 8 + ii], wb[ii * 8 + o], acc);
                    orow[bb * 8 + o] = acc;
                }
            }
        }
    }
}

// Main: CTA = one relation (blockIdx % 128), 8 warps/CTA, 6 CTAs/relation
// = 48 warps per relation, one full wave (768 CTAs, <=42 regs -> 1536
// threads/SM, occ ~75%). The relation's 4KB weight tile lives in SHARED
// MEMORY in a bank-swizzled layout (lane stride 36 words: every LDS.128
// phase touches all 32 banks exactly once -> conflict-free), freeing 32
// registers/thread vs the register-resident scheme.
// lane = 2b+h owns block b, out-half h: per point 2 half-row LDG.128,
// 8 conflict-free LDS.128 (weights), 32 FMA, 1 coalesced 512B store.
// Cells are work-stolen with depth-1 prefetch.
__global__ void __launch_bounds__(THREADS, 6)
k_main(const float4* __restrict__ x4,
       const float4* __restrict__ w4,
       float4* __restrict__ out4,
       int ncell) {
    __shared__ float s_w[32 * WSTRIDE];   // 4608 B

    int r    = blockIdx.x % NREL;
    int tid  = threadIdx.x;
    int lane = tid & 31;
    int wrp  = tid >> 5;
    int b    = lane >> 1;
    int h    = lane & 1;

    // Stage weights: thread t handles (l = t>>3, i = t&7):
    //   s_w[l*36 + i*4 .. +3] = W[r][l>>1][i][4*(l&1) .. +3]
    {
        int l  = tid >> 3;
        int i  = tid & 7;
        int bb = l >> 1;
        int hh = l & 1;
        float4 w = __ldg(w4 + (size_t)((r * 16 + bb) * 8 + i) * 2 + hh);
        *(float4*)(s_w + l * WSTRIDE + i * 4) = w;
    }
    __syncthreads();

    const float4* wl = (const float4*)(s_w + lane * WSTRIDE);  // wl[i], i<8

#define STEAL(C)                                                     \
    {                                                                \
        int t = 0;                                                   \
        if (lane == 0) t = atomicAdd(&g_cursor[r], 1);               \
        (C) = __shfl_sync(0xffffffffu, t, 0);                        \
    }

#define DO_POINT(P, XA, XB)                                                  \
    {                                                                        \
        float xs[8] = {(XA).x, (XA).y, (XA).z, (XA).w,                       \
                       (XB).x, (XB).y, (XB).z, (XB).w};                      \
        float a0 = 0.f, a1 = 0.f, a2 = 0.f, a3 = 0.f;                        \
        _Pragma("unroll")                                                    \
        for (int i = 0; i < 8; i++) {                                        \
            float4 w = wl[i];                                                \
            a0 = fmaf(xs[i], w.x, a0);                                       \
            a1 = fmaf(xs[i], w.y, a1);                                       \
            a2 = fmaf(xs[i], w.z, a2);                                       \
            a3 = fmaf(xs[i], w.w, a3);                                       \
        }                                                                    \
        out4[(size_t)(P) * 32 + lane] = make_float4(a0, a1, a2, a3);         \
    }

    int cA;
    STEAL(cA)
    int cntA = 0, pidA = 0;
    if (cA < ncell) {
        int ci = r * NBLK + cA;
        cntA = __ldg(&g_cellcnt[ci]);
        pidA = __ldg(g_pids + (size_t)ci * CELLCAP + lane);
    }

    while (cA < ncell) {
        // prefetch next cell while processing this one
        int cB;
        STEAL(cB)
        int cntB = 0, pidB = 0;
        if (cB < ncell) {
            int ci = r * NBLK + cB;
            cntB = __ldg(&g_cellcnt[ci]);
            pidB = __ldg(g_pids + (size_t)ci * CELLCAP + lane);
        }

        int k = 0;
        for (; k + 2 <= cntA; k += 2) {
            int p0 = __shfl_sync(0xffffffffu, pidA, k);
            int p1 = __shfl_sync(0xffffffffu, pidA, k + 1);
            float4 xa0 = __ldg(x4 + (size_t)p0 * 32 + 2 * b);
            float4 xb0 = __ldg(x4 + (size_t)p0 * 32 + 2 * b + 1);
            float4 xa1 = __ldg(x4 + (size_t)p1 * 32 + 2 * b);
            float4 xb1 = __ldg(x4 + (size_t)p1 * 32 + 2 * b + 1);
            DO_POINT(p0, xa0, xb0)
            DO_POINT(p1, xa1, xb1)
        }
        if (k < cntA) {
            int p = __shfl_sync(0xffffffffu, pidA, k);
            float4 xa = __ldg(x4 + (size_t)p * 32 + 2 * b);
            float4 xb = __ldg(x4 + (size_t)p * 32 + 2 * b + 1);
            DO_POINT(p, xa, xb)
        }

        cA = cB; cntA = cntB; pidA = pidB;
    }
#undef DO_POINT
#undef STEAL
}

extern "C" void kernel_launch(void* const* d_in, const int* in_sizes, int n_in,
                              void* d_out, int out_size) {
    const float* x      = (const float*)d_in[0];   // [NPTS, 128] f32
    const float* blocks = (const float*)d_in[1];   // [128,16,8,8] f32
    const int*   rel    = (const int*)d_in[2];     // [NPTS] i32
    int n = in_sizes[2];
    if (n > NPTS) n = NPTS;  // scratch bound

    int nblk = (n + SCT_PTS - 1) / SCT_PTS;        // 196
    k_scatter<<<NBLK, 256>>>(rel, n, x, blocks, (float*)d_out);
    k_main<<<GRID_MAIN, THREADS>>>(
        (const float4*)x, (const float4*)blocks, (float4*)d_out, nblk);
}

// round 8
// speedup vs baseline: 1.2522x; 1.0007x over previous
#include <cuda_runtime.h>

#define NPTS     200000
#define NREL     128
#define SCT_PTS  1024
#define NBLK     ((NPTS + SCT_PTS - 1) / SCT_PTS)   // 196
#define CELLCAP  32          // per-(relation, window) capacity; mean 8, sd 2.8
#define CTAS_PER_REL 6
#define GRID_MAIN (NREL * CTAS_PER_REL)   // 768 CTAs, single wave
#define THREADS  256
#define WSTRIDE  36          // words per lane in smem weight tile (bank swizzle)

// ---- device scratch (no allocations). Everything below is rewritten by
//      k_scatter each launch (or never consumed past the written count). ----
__device__ int g_cellcnt[NREL * NBLK];
__device__ int g_cursor[NREL];
__device__ int g_pids[NREL * NBLK * CELLCAP];

// Scatter: window blk bins its 1024 points into its OWN fixed cell per
// relation (plain stores, no global atomics). Block 0 rezeroes the
// work-stealing cursors. Overflow beyond CELLCAP (>8 sigma) computed inline.
__global__ void __launch_bounds__(256)
k_scatter(const int* __restrict__ rel, int n,
          const float* __restrict__ x,
          const float* __restrict__ w,
          float* __restrict__ out) {
    __shared__ int s_rel[SCT_PTS];
    __shared__ int s_hist[NREL];
    __shared__ int s_cur[NREL];

    int blk = blockIdx.x;
    if (blk == 0) {
        for (int i = threadIdx.x; i < NREL; i += blockDim.x) g_cursor[i] = 0;
    }

    int start = blk * SCT_PTS;
    int cnt = n - start;
    if (cnt > SCT_PTS) cnt = SCT_PTS;

    for (int i = threadIdx.x; i < NREL; i += blockDim.x) {
        s_hist[i] = 0;
        s_cur[i]  = 0;
    }
    __syncthreads();

    for (int i = threadIdx.x; i < cnt; i += blockDim.x) {
        int r = __ldg(rel + start + i);
        s_rel[i] = r;
        atomicAdd(&s_hist[r], 1);
    }
    __syncthreads();

    for (int i = threadIdx.x; i < NREL; i += blockDim.x) {
        int c = s_hist[i];
        g_cellcnt[i * NBLK + blk] = (c > CELLCAP) ? CELLCAP : c;
    }
    __syncthreads();

    for (int i = threadIdx.x; i < cnt; i += blockDim.x) {
        int r = s_rel[i];
        int pos = atomicAdd(&s_cur[r], 1);
        int p = start + i;
        if (pos < CELLCAP) {
            g_pids[(r * NBLK + blk) * CELLCAP + pos] = p;
        } else {
            // Dead-in-practice overflow: compute this point directly.
            const float* xr = x + (size_t)p * 128;
            float* orow = out + (size_t)p * 128;
            for (int bb = 0; bb < 16; bb++) {
                const float* wb = w + (size_t)((r * 16 + bb) * 8) * 8;
                for (int o = 0; o < 8; o++) {
                    float acc = 0.f;
                    for (int ii = 0; ii < 8; ii++)
                        acc = fmaf(xr[bb * 8 + ii], wb[ii * 8 + o], acc);
                    orow[bb * 8 + o] = acc;
                }
            }
        }
    }
}

// Main: CTA = one relation, 8 warps/CTA, 6 CTAs/relation = 48 warps per
// relation, single wave (768 CTAs, regs<=40 -> 1536 thr/SM). Relation's
// 4KB weight tile in SHARED MEMORY, bank-swizzled (lane stride 36 words ->
// conflict-free LDS.128). lane = 2b+h owns block b, out-half h.
// KEY CHANGE vs R7: the batch-2 inner loop is FUSED — each weight float4
// is loaded from smem ONCE and applied to BOTH points, halving the LDS
// traffic that made L1 the hottest pipe (58.6%).
__global__ void __launch_bounds__(THREADS, 6)
k_main(const float4* __restrict__ x4,
       const float4* __restrict__ w4,
       float4* __restrict__ out4,
       int ncell) {
    __shared__ float s_w[32 * WSTRIDE];   // 4608 B

    int r    = blockIdx.x % NREL;
    int tid  = threadIdx.x;
    int lane = tid & 31;
    int b    = lane >> 1;

    // Stage weights: thread t -> (l = t>>3, i = t&7):
    //   s_w[l*36 + i*4 .. +3] = W[r][l>>1][i][4*(l&1) .. +3]
    {
        int l  = tid >> 3;
        int i  = tid & 7;
        int bb = l >> 1;
        int hh = l & 1;
        float4 w = __ldg(w4 + (size_t)((r * 16 + bb) * 8 + i) * 2 + hh);
        *(float4*)(s_w + l * WSTRIDE + i * 4) = w;
    }
    __syncthreads();

    const float4* wl = (const float4*)(s_w + lane * WSTRIDE);  // wl[i], i<8

#define STEAL(C)                                                     \
    {                                                                \
        int t = 0;                                                   \
        if (lane == 0) t = atomicAdd(&g_cursor[r], 1);               \
        (C) = __shfl_sync(0xffffffffu, t, 0);                        \
    }

    int cA;
    STEAL(cA)
    int cntA = 0, pidA = 0;
    if (cA < ncell) {
        int ci = r * NBLK + cA;
        cntA = __ldg(&g_cellcnt[ci]);
        pidA = __ldg(g_pids + (size_t)ci * CELLCAP + lane);
    }

    while (cA < ncell) {
        // prefetch next cell while processing this one
        int cB;
        STEAL(cB)
        int cntB = 0, pidB = 0;
        if (cB < ncell) {
            int ci = r * NBLK + cB;
            cntB = __ldg(&g_cellcnt[ci]);
            pidB = __ldg(g_pids + (size_t)ci * CELLCAP + lane);
        }

        int k = 0;
        for (; k + 2 <= cntA; k += 2) {
            int p0 = __shfl_sync(0xffffffffu, pidA, k);
            int p1 = __shfl_sync(0xffffffffu, pidA, k + 1);
            float4 xa0 = __ldg(x4 + (size_t)p0 * 32 + 2 * b);
            float4 xb0 = __ldg(x4 + (size_t)p0 * 32 + 2 * b + 1);
            float4 xa1 = __ldg(x4 + (size_t)p1 * 32 + 2 * b);
            float4 xb1 = __ldg(x4 + (size_t)p1 * 32 + 2 * b + 1);

            float xs0[8] = {xa0.x, xa0.y, xa0.z, xa0.w,
                            xb0.x, xb0.y, xb0.z, xb0.w};
            float xs1[8] = {xa1.x, xa1.y, xa1.z, xa1.w,
                            xb1.x, xb1.y, xb1.z, xb1.w};
            float u0 = 0.f, u1 = 0.f, u2 = 0.f, u3 = 0.f;
            float v0 = 0.f, v1 = 0.f, v2 = 0.f, v3 = 0.f;
#pragma unroll
            for (int i = 0; i < 8; i++) {
                float4 w = wl[i];             // ONE LDS, used by BOTH points
                u0 = fmaf(xs0[i], w.x, u0);
                u1 = fmaf(xs0[i], w.y, u1);
                u2 = fmaf(xs0[i], w.z, u2);
                u3 = fmaf(xs0[i], w.w, u3);
                v0 = fmaf(xs1[i], w.x, v0);
                v1 = fmaf(xs1[i], w.y, v1);
                v2 = fmaf(xs1[i], w.z, v2);
                v3 = fmaf(xs1[i], w.w, v3);
            }
            out4[(size_t)p0 * 32 + lane] = make_float4(u0, u1, u2, u3);
            out4[(size_t)p1 * 32 + lane] = make_float4(v0, v1, v2, v3);
        }
        if (k < cntA) {
            int p = __shfl_sync(0xffffffffu, pidA, k);
            float4 xa = __ldg(x4 + (size_t)p * 32 + 2 * b);
            float4 xb = __ldg(x4 + (size_t)p * 32 + 2 * b + 1);
            float xs[8] = {xa.x, xa.y, xa.z, xa.w, xb.x, xb.y, xb.z, xb.w};
            float u0 = 0.f, u1 = 0.f, u2 = 0.f, u3 = 0.f;
#pragma unroll
            for (int i = 0; i < 8; i++) {
                float4 w = wl[i];
                u0 = fmaf(xs[i], w.x, u0);
                u1 = fmaf(xs[i], w.y, u1);
                u2 = fmaf(xs[i], w.z, u2);
                u3 = fmaf(xs[i], w.w, u3);
            }
            out4[(size_t)p * 32 + lane] = make_float4(u0, u1, u2, u3);
        }

        cA = cB; cntA = cntB; pidA = pidB;
    }
#undef STEAL
}

extern "C" void kernel_launch(void* const* d_in, const int* in_sizes, int n_in,
                              void* d_out, int out_size) {
    const float* x      = (const float*)d_in[0];   // [NPTS, 128] f32
    const float* blocks = (const float*)d_in[1];   // [128,16,8,8] f32
    const int*   rel    = (const int*)d_in[2];     // [NPTS] i32
    int n = in_sizes[2];
    if (n > NPTS) n = NPTS;  // scratch bound

    int nblk = (n + SCT_PTS - 1) / SCT_PTS;        // 196
    k_scatter<<<NBLK, 256>>>(rel, n, x, blocks, (float*)d_out);
    k_main<<<GRID_MAIN, THREADS>>>(
        (const float4*)x, (const float4*)blocks, (float4*)d_out, nblk);
}